// round 1
// baseline (speedup 1.0000x reference)
#include <cuda_runtime.h>

#define N_NODES 100000
#define N_EDGES 1600000
#define IN_C 128
#define OUT_C 64

// Scratch (device globals; no allocation allowed in kernel_launch)
__device__ float g_h[N_NODES * OUT_C];   // 25.6 MB — fits in L2 during scatter
__device__ int   g_deg_out[N_NODES];
__device__ int   g_deg_in[N_NODES];

// ---------------------------------------------------------------------------
// 1) zero output accumulator + degree counters
// ---------------------------------------------------------------------------
__global__ void zero_kernel(float4* __restrict__ out4) {
    int i = blockIdx.x * blockDim.x + threadIdx.x;
    int stride = gridDim.x * blockDim.x;
    const int n4 = N_NODES * OUT_C / 4;
    for (int j = i; j < n4; j += stride)
        out4[j] = make_float4(0.f, 0.f, 0.f, 0.f);
    for (int j = i; j < N_NODES; j += stride) {
        g_deg_out[j] = 0;
        g_deg_in[j]  = 0;
    }
}

// ---------------------------------------------------------------------------
// 2) degree counting
// ---------------------------------------------------------------------------
__global__ void degree_kernel(const int* __restrict__ src,
                              const int* __restrict__ dst) {
    int i = blockIdx.x * blockDim.x + threadIdx.x;
    if (i < N_EDGES) {
        atomicAdd(&g_deg_out[src[i]], 1);
        atomicAdd(&g_deg_in[dst[i]], 1);
    }
}

// ---------------------------------------------------------------------------
// 3) h = (x * norm_src) @ W     [100000,128] x [128,64] -> [100000,64]
//    16 nodes per block, 256 threads, W + x tile staged in shared memory.
// ---------------------------------------------------------------------------
__global__ __launch_bounds__(256) void gemm_kernel(const float* __restrict__ x,
                                                   const float* __restrict__ w) {
    __shared__ __align__(16) float ws[IN_C * OUT_C];   // 32 KB
    __shared__ __align__(16) float xs[16][IN_C];       // 8 KB
    __shared__ float rn[16];

    const int tid = threadIdx.x;
    const int nbase = blockIdx.x * 16;

    // stage W (coalesced, 32 elems/thread)
    #pragma unroll
    for (int i = tid; i < IN_C * OUT_C; i += 256)
        ws[i] = w[i];

    if (tid < 16) {
        int node = nbase + tid;
        float d = (node < N_NODES) ? (float)g_deg_out[node] : 1.0f;
        rn[tid] = rsqrtf(fmaxf(d, 1.0f));
    }
    __syncthreads();

    // stage x tile with source-norm applied
    for (int i = tid; i < 16 * IN_C; i += 256) {
        int r = i >> 7;            // / IN_C
        int c = i & (IN_C - 1);
        int node = nbase + r;
        xs[r][c] = (node < N_NODES) ? x[(long long)node * IN_C + c] * rn[r] : 0.0f;
    }
    __syncthreads();

    const int ni = tid >> 4;            // node-in-tile 0..15
    const int c0 = (tid & 15) * 4;      // output column base

    float4 acc = make_float4(0.f, 0.f, 0.f, 0.f);
    #pragma unroll 16
    for (int k = 0; k < IN_C; k++) {
        float xv = xs[ni][k];
        float4 wv = *(const float4*)&ws[k * OUT_C + c0];
        acc.x += xv * wv.x;
        acc.y += xv * wv.y;
        acc.z += xv * wv.z;
        acc.w += xv * wv.w;
    }

    int node = nbase + ni;
    if (node < N_NODES)
        *(float4*)&g_h[node * OUT_C + c0] = acc;
}

// ---------------------------------------------------------------------------
// 4) edge scatter: out[dst] += h[src]
//    16 threads per edge, each owns one float4 column group.
//    Vectorized red.global.add.v4.f32 (sm_90+) — 1 RED.128 per thread.
// ---------------------------------------------------------------------------
__global__ __launch_bounds__(256) void scatter_kernel(const int* __restrict__ src,
                                                      const int* __restrict__ dst,
                                                      float* __restrict__ out) {
    long long id = (long long)blockIdx.x * blockDim.x + threadIdx.x;
    if (id >= (long long)N_EDGES * 16) return;
    int e = (int)(id >> 4);
    int g = (int)(id & 15);

    int s = __ldg(&src[e]);
    int d = __ldg(&dst[e]);

    const float4 v = *(const float4*)&g_h[s * OUT_C + g * 4];
    float* p = &out[(long long)d * OUT_C + g * 4];

    asm volatile("red.global.add.v4.f32 [%0], {%1, %2, %3, %4};"
                 :: "l"(p), "f"(v.x), "f"(v.y), "f"(v.z), "f"(v.w)
                 : "memory");
}

// ---------------------------------------------------------------------------
// 5) finalize: out = out * norm_dst + bias
// ---------------------------------------------------------------------------
__global__ void finalize_kernel(float4* __restrict__ out4,
                                const float4* __restrict__ bias4) {
    int i = blockIdx.x * blockDim.x + threadIdx.x;
    const int n4 = N_NODES * OUT_C / 4;
    if (i >= n4) return;
    int node = i / (OUT_C / 4);
    int cg   = i & (OUT_C / 4 - 1);
    float rn = rsqrtf(fmaxf((float)g_deg_in[node], 1.0f));
    float4 v = out4[i];
    float4 b = bias4[cg];
    v.x = v.x * rn + b.x;
    v.y = v.y * rn + b.y;
    v.z = v.z * rn + b.z;
    v.w = v.w * rn + b.w;
    out4[i] = v;
}

// ---------------------------------------------------------------------------
extern "C" void kernel_launch(void* const* d_in, const int* in_sizes, int n_in,
                              void* d_out, int out_size) {
    const float* x      = (const float*)d_in[0];
    const float* weight = (const float*)d_in[1];
    const float* bias   = (const float*)d_in[2];
    const int*   src    = (const int*)d_in[3];
    const int*   dst    = (const int*)d_in[4];
    float* out = (float*)d_out;

    // 1) zero accumulator + degree counters
    zero_kernel<<<1024, 256>>>((float4*)out);

    // 2) degrees
    degree_kernel<<<(N_EDGES + 255) / 256, 256>>>(src, dst);

    // 3) h = (x * norm_src) @ W
    gemm_kernel<<<(N_NODES + 15) / 16, 256>>>(x, weight);

    // 4) scatter-add over edges
    long long items = (long long)N_EDGES * 16;
    scatter_kernel<<<(int)((items + 255) / 256), 256>>>(src, dst, out);

    // 5) scale + bias
    finalize_kernel<<<(N_NODES * OUT_C / 4 + 255) / 256, 256>>>((float4*)out,
                                                                 (const float4*)bias);
}

// round 2
// speedup vs baseline: 1.3674x; 1.3674x over previous
#include <cuda_runtime.h>

#define N_NODES 100000
#define N_EDGES 1600000
#define IN_C 128
#define OUT_C 64

#define SCAN_BLOCK 1024
#define N_SCAN_BLOCKS ((N_NODES + SCAN_BLOCK - 1) / SCAN_BLOCK)   // 98

// ------------------------- device scratch (no alloc allowed) ----------------
__device__ float g_h[N_NODES * OUT_C];     // 25.6 MB (L2-resident)
__device__ int   g_deg_out[N_NODES];
__device__ int   g_deg_in[N_NODES];
__device__ int   g_row_start[N_NODES];     // exclusive scan of deg_in
__device__ int   g_cursor[N_NODES];
__device__ int   g_esrc[N_EDGES];          // src indices grouped by dst
__device__ int   g_bsum[N_SCAN_BLOCKS];
__device__ int   g_boff[N_SCAN_BLOCKS];

// ---------------------------------------------------------------------------
// 1) zero degree counters
// ---------------------------------------------------------------------------
__global__ void init_kernel() {
    int i = blockIdx.x * blockDim.x + threadIdx.x;
    int stride = gridDim.x * blockDim.x;
    for (int j = i; j < N_NODES; j += stride) {
        g_deg_out[j] = 0;
        g_deg_in[j]  = 0;
    }
}

// ---------------------------------------------------------------------------
// 2) degree counting (RED.ADD, spread addresses)
// ---------------------------------------------------------------------------
__global__ void degree_kernel(const int* __restrict__ src,
                              const int* __restrict__ dst) {
    int i = blockIdx.x * blockDim.x + threadIdx.x;
    if (i < N_EDGES) {
        atomicAdd(&g_deg_out[src[i]], 1);
        atomicAdd(&g_deg_in[dst[i]], 1);
    }
}

// ---------------------------------------------------------------------------
// 3) block-level inclusive scan of deg_in -> chunk-local exclusive + totals
// ---------------------------------------------------------------------------
__global__ __launch_bounds__(SCAN_BLOCK) void scan_block_kernel() {
    __shared__ int sh[SCAN_BLOCK];
    int t = threadIdx.x;
    int i = blockIdx.x * SCAN_BLOCK + t;
    int v = (i < N_NODES) ? g_deg_in[i] : 0;
    sh[t] = v;
    __syncthreads();
    #pragma unroll
    for (int off = 1; off < SCAN_BLOCK; off <<= 1) {
        int add = (t >= off) ? sh[t - off] : 0;
        __syncthreads();
        sh[t] += add;
        __syncthreads();
    }
    if (i < N_NODES) g_row_start[i] = sh[t] - v;   // exclusive (chunk-local)
    if (t == SCAN_BLOCK - 1) g_bsum[blockIdx.x] = sh[t];
}

__global__ void scan_bsum_kernel() {
    __shared__ int sh[128];
    int t = threadIdx.x;
    int v = (t < N_SCAN_BLOCKS) ? g_bsum[t] : 0;
    sh[t] = v;
    __syncthreads();
    #pragma unroll
    for (int off = 1; off < 128; off <<= 1) {
        int add = (t >= off) ? sh[t - off] : 0;
        __syncthreads();
        sh[t] += add;
        __syncthreads();
    }
    if (t < N_SCAN_BLOCKS) g_boff[t] = sh[t] - v;  // exclusive
}

__global__ void add_offsets_kernel() {
    int i = blockIdx.x * blockDim.x + threadIdx.x;
    if (i < N_NODES) {
        int rs = g_row_start[i] + g_boff[i >> 10];
        g_row_start[i] = rs;
        g_cursor[i]    = rs;
    }
}

// ---------------------------------------------------------------------------
// 4) CSR fill: group src indices by dst
// ---------------------------------------------------------------------------
__global__ void csr_fill_kernel(const int* __restrict__ src,
                                const int* __restrict__ dst) {
    int i = blockIdx.x * blockDim.x + threadIdx.x;
    if (i < N_EDGES) {
        int d = dst[i];
        int pos = atomicAdd(&g_cursor[d], 1);
        g_esrc[pos] = src[i];
    }
}

// ---------------------------------------------------------------------------
// 5) GEMM: h = (x * norm_src) @ W   via packed fma.rn.f32x2
//    thread-per-node: 64 output cols in 32 f32x2 registers.
//    W rows read via broadcast LDS (all lanes same address -> free).
//    x staged in smem transposed (pad 257 -> conflict-free both ways).
//    norm_src folded into the final store (h = rn * (x @ W)).
// ---------------------------------------------------------------------------
__global__ __launch_bounds__(256) void gemm_kernel(const float* __restrict__ x,
                                                   const float* __restrict__ w) {
    __shared__ __align__(16) float ws[32 * OUT_C];     // 8 KB  (k-chunk of W)
    __shared__ float xs[32][257];                      // 32.9 KB (k-chunk of x, transposed)

    const int t = threadIdx.x;
    const int nbase = blockIdx.x * 256;
    const int node = nbase + t;

    unsigned long long acc[32];
    #pragma unroll
    for (int c = 0; c < 32; c++) acc[c] = 0ULL;

    for (int kc = 0; kc < 4; kc++) {
        __syncthreads();
        // stage W chunk [32 x 64] (coalesced, 8 floats/thread)
        #pragma unroll
        for (int j = 0; j < 8; j++)
            ws[t + 256 * j] = w[(kc * 32) * OUT_C + t + 256 * j];
        // stage x chunk [256 nodes x 32 k] transposed, coalesced global reads
        #pragma unroll
        for (int j = 0; j < 32; j++) {
            int i = t + 256 * j;
            int nl = i >> 5;
            int kk = i & 31;
            int nd = nbase + nl;
            float v = (nd < N_NODES) ? x[nd * IN_C + kc * 32 + kk] : 0.0f;
            xs[kk][nl] = v;
        }
        __syncthreads();

        #pragma unroll
        for (int kk = 0; kk < 32; kk++) {
            float xv = xs[kk][t];
            unsigned long long xv2;
            asm("mov.b64 %0, {%1, %1};" : "=l"(xv2) : "r"(__float_as_uint(xv)));
            const ulonglong2* wrow = (const ulonglong2*)&ws[kk * OUT_C];
            #pragma unroll
            for (int c = 0; c < 16; c++) {
                ulonglong2 w2 = wrow[c];   // LDS.128, broadcast across warp
                asm("fma.rn.f32x2 %0, %1, %2, %0;" : "+l"(acc[2 * c])     : "l"(xv2), "l"(w2.x));
                asm("fma.rn.f32x2 %0, %1, %2, %0;" : "+l"(acc[2 * c + 1]) : "l"(xv2), "l"(w2.y));
            }
        }
    }

    if (node < N_NODES) {
        float rn = rsqrtf(fmaxf((float)g_deg_out[node], 1.0f));
        float* hp = &g_h[node * OUT_C];
        #pragma unroll
        for (int c = 0; c < 16; c++) {
            unsigned int l0, h0, l1, h1;
            asm("mov.b64 {%0, %1}, %2;" : "=r"(l0), "=r"(h0) : "l"(acc[2 * c]));
            asm("mov.b64 {%0, %1}, %2;" : "=r"(l1), "=r"(h1) : "l"(acc[2 * c + 1]));
            float4 v;
            v.x = __uint_as_float(l0) * rn;
            v.y = __uint_as_float(h0) * rn;
            v.z = __uint_as_float(l1) * rn;
            v.w = __uint_as_float(h1) * rn;
            *(float4*)&hp[c * 4] = v;
        }
    }
}

// ---------------------------------------------------------------------------
// 6) pull-mode aggregation: out[n] = norm_dst[n] * sum_{e: dst=n} h[src_e] + bias
//    16 threads per node (one float4 col group each), 2 nodes per warp.
//    Registers accumulate; single write; no atomics, no zero, no finalize.
// ---------------------------------------------------------------------------
__global__ __launch_bounds__(256) void aggregate_kernel(const float4* __restrict__ bias4,
                                                        float* __restrict__ out) {
    int gwarp = (blockIdx.x * 256 + threadIdx.x) >> 5;
    int lane  = threadIdx.x & 31;
    int node  = gwarp * 2 + (lane >> 4);
    if (node >= N_NODES) return;
    int g = lane & 15;

    int start = g_row_start[node];
    int cnt   = g_deg_in[node];
    const int* ep = &g_esrc[start];

    float4 acc = make_float4(0.f, 0.f, 0.f, 0.f);
    int j = 0;
    for (; j + 4 <= cnt; j += 4) {
        int s0 = ep[j], s1 = ep[j + 1], s2 = ep[j + 2], s3 = ep[j + 3];
        float4 v0 = *(const float4*)&g_h[s0 * OUT_C + g * 4];
        float4 v1 = *(const float4*)&g_h[s1 * OUT_C + g * 4];
        float4 v2 = *(const float4*)&g_h[s2 * OUT_C + g * 4];
        float4 v3 = *(const float4*)&g_h[s3 * OUT_C + g * 4];
        acc.x += (v0.x + v1.x) + (v2.x + v3.x);
        acc.y += (v0.y + v1.y) + (v2.y + v3.y);
        acc.z += (v0.z + v1.z) + (v2.z + v3.z);
        acc.w += (v0.w + v1.w) + (v2.w + v3.w);
    }
    for (; j < cnt; j++) {
        int s = ep[j];
        float4 v = *(const float4*)&g_h[s * OUT_C + g * 4];
        acc.x += v.x; acc.y += v.y; acc.z += v.z; acc.w += v.w;
    }

    float rn = rsqrtf(fmaxf((float)cnt, 1.0f));
    float4 b = bias4[g];
    float4 r;
    r.x = acc.x * rn + b.x;
    r.y = acc.y * rn + b.y;
    r.z = acc.z * rn + b.z;
    r.w = acc.w * rn + b.w;
    *(float4*)&out[node * OUT_C + g * 4] = r;
}

// ---------------------------------------------------------------------------
extern "C" void kernel_launch(void* const* d_in, const int* in_sizes, int n_in,
                              void* d_out, int out_size) {
    const float* x      = (const float*)d_in[0];
    const float* weight = (const float*)d_in[1];
    const float* bias   = (const float*)d_in[2];
    const int*   src    = (const int*)d_in[3];
    const int*   dst    = (const int*)d_in[4];
    float* out = (float*)d_out;

    init_kernel<<<256, 256>>>();
    degree_kernel<<<(N_EDGES + 255) / 256, 256>>>(src, dst);

    // CSR offsets (exclusive scan of deg_in)
    scan_block_kernel<<<N_SCAN_BLOCKS, SCAN_BLOCK>>>();
    scan_bsum_kernel<<<1, 128>>>();
    add_offsets_kernel<<<(N_NODES + 255) / 256, 256>>>();

    // h = (x * norm_src) @ W   (needs deg_out only)
    gemm_kernel<<<(N_NODES + 255) / 256, 256>>>(x, weight);

    // group edges by dst
    csr_fill_kernel<<<(N_EDGES + 255) / 256, 256>>>(src, dst);

    // pull aggregation + norm_dst + bias, single write
    int nwarps = (N_NODES + 1) / 2;
    aggregate_kernel<<<(nwarps + 7) / 8, 256>>>((const float4*)bias, out);
}

// round 3
// speedup vs baseline: 1.4109x; 1.0319x over previous
#include <cuda_runtime.h>

#define N_NODES 100000
#define N_EDGES 1600000
#define IN_C 128
#define OUT_C 64

#define SCAN_BLOCK 1024
#define N_SCAN_BLOCKS ((N_NODES + SCAN_BLOCK - 1) / SCAN_BLOCK)   // 98

// ------------------------- device scratch (no alloc allowed) ----------------
__device__ float g_h[N_NODES * OUT_C];     // 25.6 MB (L2-resident)
__device__ int   g_degs[2 * N_NODES];      // [0,N): deg_out   [N,2N): deg_in
__device__ int   g_row_start[N_NODES];     // excl scan of deg_in; after fill = row END
__device__ int   g_esrc[N_EDGES];          // src indices grouped by dst
__device__ int   g_bsum[N_SCAN_BLOCKS];

// ---------------------------------------------------------------------------
// 1) degree counting — int4-vectorized, streaming index reads
// ---------------------------------------------------------------------------
__global__ __launch_bounds__(256) void degree_kernel(const int4* __restrict__ src4,
                                                     const int4* __restrict__ dst4) {
    int i = blockIdx.x * blockDim.x + threadIdx.x;
    if (i < N_EDGES / 4) {
        int4 s = __ldcs(&src4[i]);
        int4 d = __ldcs(&dst4[i]);
        atomicAdd(&g_degs[s.x], 1);
        atomicAdd(&g_degs[s.y], 1);
        atomicAdd(&g_degs[s.z], 1);
        atomicAdd(&g_degs[s.w], 1);
        atomicAdd(&g_degs[N_NODES + d.x], 1);
        atomicAdd(&g_degs[N_NODES + d.y], 1);
        atomicAdd(&g_degs[N_NODES + d.z], 1);
        atomicAdd(&g_degs[N_NODES + d.w], 1);
    }
}

// ---------------------------------------------------------------------------
// 2) block-level scan of deg_in -> chunk-local exclusive prefix + block totals
// ---------------------------------------------------------------------------
__global__ __launch_bounds__(SCAN_BLOCK) void scan_block_kernel() {
    __shared__ int sh[SCAN_BLOCK];
    int t = threadIdx.x;
    int i = blockIdx.x * SCAN_BLOCK + t;
    int v = (i < N_NODES) ? g_degs[N_NODES + i] : 0;
    sh[t] = v;
    __syncthreads();
    #pragma unroll
    for (int off = 1; off < SCAN_BLOCK; off <<= 1) {
        int add = (t >= off) ? sh[t - off] : 0;
        __syncthreads();
        sh[t] += add;
        __syncthreads();
    }
    if (i < N_NODES) g_row_start[i] = sh[t] - v;   // exclusive (chunk-local)
    if (t == SCAN_BLOCK - 1) g_bsum[blockIdx.x] = sh[t];
}

// ---------------------------------------------------------------------------
// 3) every block scans the 98 block-sums in smem and adds its offset.
//    (replaces a dedicated single-block kernel + a cursor-copy kernel)
// ---------------------------------------------------------------------------
__global__ __launch_bounds__(SCAN_BLOCK) void add_offsets_kernel() {
    __shared__ int sh[128];
    int t = threadIdx.x;
    if (t < 128) sh[t] = (t < N_SCAN_BLOCKS) ? g_bsum[t] : 0;
    __syncthreads();
    #pragma unroll
    for (int off = 1; off < 128; off <<= 1) {
        int add = (t < 128 && t >= off) ? sh[t - off] : 0;
        __syncthreads();
        if (t < 128) sh[t] += add;
        __syncthreads();
    }
    int i = blockIdx.x * SCAN_BLOCK + t;
    if (i < N_NODES) {
        int excl = sh[blockIdx.x] - g_bsum[blockIdx.x];  // inclusive - own = exclusive
        g_row_start[i] += excl;
    }
}

// ---------------------------------------------------------------------------
// 4) CSR fill: group src indices by dst.  g_row_start doubles as the cursor;
//    after this kernel g_row_start[d] == row END of d.
// ---------------------------------------------------------------------------
__global__ __launch_bounds__(256) void csr_fill_kernel(const int4* __restrict__ src4,
                                                       const int4* __restrict__ dst4) {
    int i = blockIdx.x * blockDim.x + threadIdx.x;
    if (i < N_EDGES / 4) {
        int4 s = __ldcs(&src4[i]);
        int4 d = __ldcs(&dst4[i]);
        g_esrc[atomicAdd(&g_row_start[d.x], 1)] = s.x;
        g_esrc[atomicAdd(&g_row_start[d.y], 1)] = s.y;
        g_esrc[atomicAdd(&g_row_start[d.z], 1)] = s.z;
        g_esrc[atomicAdd(&g_row_start[d.w], 1)] = s.w;
    }
}

// ---------------------------------------------------------------------------
// 5) GEMM: h = (x * norm_src) @ W   via packed fma.rn.f32x2
// ---------------------------------------------------------------------------
__global__ __launch_bounds__(256) void gemm_kernel(const float* __restrict__ x,
                                                   const float* __restrict__ w) {
    __shared__ __align__(16) float ws[32 * OUT_C];     // 8 KB  (k-chunk of W)
    __shared__ float xs[32][257];                      // 32.9 KB (k-chunk of x, transposed)

    const int t = threadIdx.x;
    const int nbase = blockIdx.x * 256;
    const int node = nbase + t;

    unsigned long long acc[32];
    #pragma unroll
    for (int c = 0; c < 32; c++) acc[c] = 0ULL;

    for (int kc = 0; kc < 4; kc++) {
        __syncthreads();
        #pragma unroll
        for (int j = 0; j < 8; j++)
            ws[t + 256 * j] = w[(kc * 32) * OUT_C + t + 256 * j];
        #pragma unroll
        for (int j = 0; j < 32; j++) {
            int i = t + 256 * j;
            int nl = i >> 5;
            int kk = i & 31;
            int nd = nbase + nl;
            float v = (nd < N_NODES) ? __ldcs(&x[nd * IN_C + kc * 32 + kk]) : 0.0f;
            xs[kk][nl] = v;
        }
        __syncthreads();

        #pragma unroll
        for (int kk = 0; kk < 32; kk++) {
            float xv = xs[kk][t];
            unsigned long long xv2;
            asm("mov.b64 %0, {%1, %1};" : "=l"(xv2) : "r"(__float_as_uint(xv)));
            const ulonglong2* wrow = (const ulonglong2*)&ws[kk * OUT_C];
            #pragma unroll
            for (int c = 0; c < 16; c++) {
                ulonglong2 w2 = wrow[c];   // LDS.128, broadcast across warp
                asm("fma.rn.f32x2 %0, %1, %2, %0;" : "+l"(acc[2 * c])     : "l"(xv2), "l"(w2.x));
                asm("fma.rn.f32x2 %0, %1, %2, %0;" : "+l"(acc[2 * c + 1]) : "l"(xv2), "l"(w2.y));
            }
        }
    }

    if (node < N_NODES) {
        float rn = rsqrtf(fmaxf((float)g_degs[node], 1.0f));
        float* hp = &g_h[node * OUT_C];
        #pragma unroll
        for (int c = 0; c < 16; c++) {
            unsigned int l0, h0, l1, h1;
            asm("mov.b64 {%0, %1}, %2;" : "=r"(l0), "=r"(h0) : "l"(acc[2 * c]));
            asm("mov.b64 {%0, %1}, %2;" : "=r"(l1), "=r"(h1) : "l"(acc[2 * c + 1]));
            float4 v;
            v.x = __uint_as_float(l0) * rn;
            v.y = __uint_as_float(h0) * rn;
            v.z = __uint_as_float(l1) * rn;
            v.w = __uint_as_float(h1) * rn;
            *(float4*)&hp[c * 4] = v;
        }
    }
}

// ---------------------------------------------------------------------------
// 6) pull aggregation: out[n] = norm_dst[n] * sum h[src_e] + bias
//    16 threads/node (one float4 each), 2 nodes/warp, 8-deep gather unroll.
// ---------------------------------------------------------------------------
__global__ __launch_bounds__(256) void aggregate_kernel(const float4* __restrict__ bias4,
                                                        float* __restrict__ out) {
    int gwarp = (blockIdx.x * 256 + threadIdx.x) >> 5;
    int lane  = threadIdx.x & 31;
    int node  = gwarp * 2 + (lane >> 4);
    if (node >= N_NODES) return;
    int g = lane & 15;

    int cnt = g_degs[N_NODES + node];
    int start = g_row_start[node] - cnt;     // row_start was bumped to END by fill
    const int* ep = &g_esrc[start];

    float4 acc = make_float4(0.f, 0.f, 0.f, 0.f);
    int j = 0;
    for (; j + 8 <= cnt; j += 8) {
        int s0 = ep[j],     s1 = ep[j + 1], s2 = ep[j + 2], s3 = ep[j + 3];
        int s4 = ep[j + 4], s5 = ep[j + 5], s6 = ep[j + 6], s7 = ep[j + 7];
        float4 v0 = *(const float4*)&g_h[s0 * OUT_C + g * 4];
        float4 v1 = *(const float4*)&g_h[s1 * OUT_C + g * 4];
        float4 v2 = *(const float4*)&g_h[s2 * OUT_C + g * 4];
        float4 v3 = *(const float4*)&g_h[s3 * OUT_C + g * 4];
        float4 v4 = *(const float4*)&g_h[s4 * OUT_C + g * 4];
        float4 v5 = *(const float4*)&g_h[s5 * OUT_C + g * 4];
        float4 v6 = *(const float4*)&g_h[s6 * OUT_C + g * 4];
        float4 v7 = *(const float4*)&g_h[s7 * OUT_C + g * 4];
        acc.x += ((v0.x + v1.x) + (v2.x + v3.x)) + ((v4.x + v5.x) + (v6.x + v7.x));
        acc.y += ((v0.y + v1.y) + (v2.y + v3.y)) + ((v4.y + v5.y) + (v6.y + v7.y));
        acc.z += ((v0.z + v1.z) + (v2.z + v3.z)) + ((v4.z + v5.z) + (v6.z + v7.z));
        acc.w += ((v0.w + v1.w) + (v2.w + v3.w)) + ((v4.w + v5.w) + (v6.w + v7.w));
    }
    for (; j < cnt; j++) {
        int s = ep[j];
        float4 v = *(const float4*)&g_h[s * OUT_C + g * 4];
        acc.x += v.x; acc.y += v.y; acc.z += v.z; acc.w += v.w;
    }

    float rn = rsqrtf(fmaxf((float)cnt, 1.0f));
    float4 b = bias4[g];
    float4 r;
    r.x = acc.x * rn + b.x;
    r.y = acc.y * rn + b.y;
    r.z = acc.z * rn + b.z;
    r.w = acc.w * rn + b.w;
    __stcs((float4*)&out[node * OUT_C + g * 4], r);
}

// ---------------------------------------------------------------------------
extern "C" void kernel_launch(void* const* d_in, const int* in_sizes, int n_in,
                              void* d_out, int out_size) {
    const float* x      = (const float*)d_in[0];
    const float* weight = (const float*)d_in[1];
    const float* bias   = (const float*)d_in[2];
    const int*   src    = (const int*)d_in[3];
    const int*   dst    = (const int*)d_in[4];
    float* out = (float*)d_out;

    // zero degree counters via memset node (DMA, replaces init kernel)
    void* degs_ptr = nullptr;
    cudaGetSymbolAddress(&degs_ptr, g_degs);
    cudaMemsetAsync(degs_ptr, 0, 2 * N_NODES * sizeof(int));

    degree_kernel<<<(N_EDGES / 4 + 255) / 256, 256>>>((const int4*)src, (const int4*)dst);

    // CSR offsets (exclusive scan of deg_in), 2 kernels
    scan_block_kernel<<<N_SCAN_BLOCKS, SCAN_BLOCK>>>();
    add_offsets_kernel<<<N_SCAN_BLOCKS, SCAN_BLOCK>>>();

    // h = (x * norm_src) @ W   (needs deg_out only)
    gemm_kernel<<<(N_NODES + 255) / 256, 256>>>(x, weight);

    // group edges by dst (row_start becomes row end)
    csr_fill_kernel<<<(N_EDGES / 4 + 255) / 256, 256>>>((const int4*)src, (const int4*)dst);

    // pull aggregation + norm_dst + bias, single write
    int nwarps = (N_NODES + 1) / 2;
    aggregate_kernel<<<(nwarps + 7) / 8, 256>>>((const float4*)bias, out);
}